// round 14
// baseline (speedup 1.0000x reference)
#include <cuda_runtime.h>
#include <cuda_fp16.h>
#include <math.h>
#include <stdint.h>

// ---------------------------------------------------------------------------
// Problem constants
// ---------------------------------------------------------------------------
#define BATCH   32
#define HIMG    56
#define WIMG    56
#define CDIM    384
#define LTOK    (HIMG*WIMG)          // 3136
#define NHEADS  12
#define HD      32
#define WS      7
#define NWIN_T  49
#define SHIFT   3
#define NWX     8
#define NWIN    64
#define BN      (BATCH*NWIN)         // 2048 windows
#define MTOK    (BN*NWIN_T)          // 100352 tokens
#define HID     1536

// ---------------------------------------------------------------------------
// Scratch (device globals)
// ---------------------------------------------------------------------------
__device__ __half g_qkv [(size_t)MTOK * 3 * CDIM];
__device__ float  g_proj[(size_t)MTOK * CDIM];
__device__ float  g_y   [(size_t)MTOK * CDIM];
__device__ __half g_win [(size_t)MTOK * CDIM];
__device__ __half g_att [(size_t)MTOK * CDIM];
__device__ __half g_h2  [(size_t)MTOK * CDIM];
__device__ __half g_mlp [(size_t)MTOK * HID];
// transposed weights Wt[N][K], fp16
__device__ __half g_wq[3*CDIM*CDIM];
__device__ __half g_wp[CDIM*CDIM];
__device__ __half g_w1[HID*CDIM];
__device__ __half g_w2[CDIM*HID];

// ---------------------------------------------------------------------------
// Helpers
// ---------------------------------------------------------------------------
static __device__ __forceinline__ uint32_t s2u(const void* p) {
    return (uint32_t)__cvta_generic_to_shared(p);
}
static __device__ __forceinline__ void ldm4(uint32_t& d0, uint32_t& d1, uint32_t& d2,
                                            uint32_t& d3, uint32_t a) {
    asm volatile("ldmatrix.sync.aligned.m8n8.x4.shared.b16 {%0,%1,%2,%3},[%4];"
                 : "=r"(d0), "=r"(d1), "=r"(d2), "=r"(d3) : "r"(a));
}
static __device__ __forceinline__ void mma_f16(float* c, const uint32_t* a, const uint32_t* b) {
    asm volatile("mma.sync.aligned.m16n8k16.row.col.f32.f16.f16.f32 "
                 "{%0,%1,%2,%3},{%4,%5,%6,%7},{%8,%9},{%0,%1,%2,%3};"
                 : "+f"(c[0]), "+f"(c[1]), "+f"(c[2]), "+f"(c[3])
                 : "r"(a[0]), "r"(a[1]), "r"(a[2]), "r"(a[3]), "r"(b[0]), "r"(b[1]));
}
static __device__ __forceinline__ void cpa16(uint32_t dst, const void* src) {
    asm volatile("cp.async.cg.shared.global [%0], [%1], 16;"
                 :: "r"(dst), "l"(src) : "memory");
}

// ---------------------------------------------------------------------------
// fp16 MMA GEMM (unchanged from R13): 128x128 tile, BK=64, 3-stage, 2 CTAs/SM.
// ---------------------------------------------------------------------------
#define TILE_B   (128*128)
#define STAGE_B  (2*TILE_B)
#define NSTAGE   3
#define GEMM_SMEM (NSTAGE*STAGE_B)

template <int EPI>
__global__ __launch_bounds__(256, 2)
void mma_gemm(const __half* __restrict__ A, const __half* __restrict__ B,
              const float* __restrict__ bias, const float* __restrict__ res,
              float* __restrict__ Cf, __half* __restrict__ Cm, int N, int K)
{
    extern __shared__ char sm[];
    const int tid  = threadIdx.x, lane = tid & 31, warp = tid >> 5;
    const int m0 = blockIdx.y * 128, n0 = blockIdx.x * 128;
    const int wm = (warp >> 2) * 64, wn = (warp & 3) * 32;

    const int cr = tid >> 1, g0 = (tid & 1) * 4;
    const __half* pA = A + (size_t)(m0 + cr) * K;
    const __half* pB = B + (size_t)(n0 + cr) * K;
    const uint32_t swc = (uint32_t)cr & 7;
    uint32_t so[4];
    #pragma unroll
    for (int j = 0; j < 4; j++)
        so[j] = (uint32_t)cr * 128 + ((((uint32_t)(g0 + j)) ^ swc) << 4);
    const uint32_t smb = s2u(sm);
    const int nch = K >> 6;

    auto issue_stage = [&](int i, int s) {
        int k0 = i << 6;
        uint32_t b = smb + (uint32_t)s * STAGE_B;
        #pragma unroll
        for (int j = 0; j < 4; j++) {
            cpa16(b + so[j],          pA + k0 + (g0 + j) * 8);
            cpa16(b + TILE_B + so[j], pB + k0 + (g0 + j) * 8);
        }
        asm volatile("cp.async.commit_group;" ::: "memory");
    };

    float acc[4][4][4];
    #pragma unroll
    for (int i = 0; i < 4; i++)
        #pragma unroll
        for (int j = 0; j < 4; j++)
            #pragma unroll
            for (int k = 0; k < 4; k++) acc[i][j][k] = 0.0f;

    const int tsel = lane >> 3, rlo = lane & 7;
    const uint32_t rA = (uint32_t)(wm + rlo + (tsel & 1) * 8);
    const uint32_t gA = (uint32_t)(tsel >> 1);
    const uint32_t rB = (uint32_t)(wn + rlo + (tsel >> 1) * 8);
    const uint32_t gB = (uint32_t)(tsel & 1);

    issue_stage(0, 0);
    if (nch > 1) issue_stage(1, 1);

    int stage = 0;
    for (int i = 0; i < nch; i++) {
        if (i + 1 < nch) asm volatile("cp.async.wait_group 1;" ::: "memory");
        else             asm volatile("cp.async.wait_group 0;" ::: "memory");
        __syncthreads();

        if (i + 2 < nch) {
            int s = stage + 2; if (s >= NSTAGE) s -= NSTAGE;
            issue_stage(i + 2, s);
        }

        const uint32_t sb = smb + (uint32_t)stage * STAGE_B;
        #pragma unroll
        for (int kst = 0; kst < 4; kst++) {
            uint32_t bfr[4][2];
            #pragma unroll
            for (int p = 0; p < 2; p++) {
                uint32_t row = rB + p * 16;
                uint32_t ad  = sb + TILE_B + row * 128 + (((gB + kst*2u) ^ (uint32_t)rlo) << 4);
                ldm4(bfr[2*p][0], bfr[2*p][1], bfr[2*p+1][0], bfr[2*p+1][1], ad);
            }
            #pragma unroll
            for (int mf = 0; mf < 4; mf++) {
                uint32_t row = rA + mf * 16;
                uint32_t ad  = sb + row * 128 + (((gA + kst*2u) ^ (uint32_t)rlo) << 4);
                uint32_t afr[4];
                ldm4(afr[0], afr[1], afr[2], afr[3], ad);
                #pragma unroll
                for (int nf = 0; nf < 4; nf++)
                    mma_f16(acc[mf][nf], afr, bfr[nf]);
            }
        }
        stage++; if (stage >= NSTAGE) stage = 0;
    }
    __syncthreads();

    const int qr = lane >> 2, qc = (lane & 3) * 2;
    #pragma unroll
    for (int mf = 0; mf < 4; mf++) {
        int row = m0 + wm + mf * 16 + qr;
        #pragma unroll
        for (int nf = 0; nf < 4; nf++) {
            int col = n0 + wn + nf * 8 + qc;
            float b0 = bias[col], b1 = bias[col + 1];
            float v0 = acc[mf][nf][0] + b0, v1 = acc[mf][nf][1] + b1;
            float v2 = acc[mf][nf][2] + b0, v3 = acc[mf][nf][3] + b1;
            if (EPI == 0) {
                *(float2*)(Cf + (size_t)row * N + col)       = make_float2(v0, v1);
                *(float2*)(Cf + (size_t)(row + 8) * N + col) = make_float2(v2, v3);
            } else if (EPI == 1) {
                v0 = 0.5f * v0 * (1.0f + erff(v0 * 0.70710678118654752f));
                v1 = 0.5f * v1 * (1.0f + erff(v1 * 0.70710678118654752f));
                v2 = 0.5f * v2 * (1.0f + erff(v2 * 0.70710678118654752f));
                v3 = 0.5f * v3 * (1.0f + erff(v3 * 0.70710678118654752f));
                *(__half2*)(Cm + (size_t)row * N + col)       = __floats2half2_rn(v0, v1);
                *(__half2*)(Cm + (size_t)(row + 8) * N + col) = __floats2half2_rn(v2, v3);
            } else if (EPI == 2) {
                float2 r0v = *(const float2*)(res + (size_t)row * N + col);
                float2 r1v = *(const float2*)(res + (size_t)(row + 8) * N + col);
                *(float2*)(Cf + (size_t)row * N + col)       = make_float2(v0 + r0v.x, v1 + r0v.y);
                *(float2*)(Cf + (size_t)(row + 8) * N + col) = make_float2(v2 + r1v.x, v3 + r1v.y);
            } else {
                *(__half2*)(Cm + (size_t)row * N + col)       = __floats2half2_rn(v0, v1);
                *(__half2*)(Cm + (size_t)(row + 8) * N + col) = __floats2half2_rn(v2, v3);
            }
        }
    }
}

// ---------------------------------------------------------------------------
// Weight transpose + fp16 round
// ---------------------------------------------------------------------------
__global__ __launch_bounds__(256)
void wtrans_kernel(const float* __restrict__ W, __half* __restrict__ Wt, int K, int N)
{
    __shared__ float t[32][33];
    int tx = threadIdx.x & 31, ty = threadIdx.x >> 5;
    int kb = blockIdx.y * 32, nb = blockIdx.x * 32;
    #pragma unroll
    for (int j = ty; j < 32; j += 8)
        t[j][tx] = W[(size_t)(kb + j) * N + nb + tx];
    __syncthreads();
    #pragma unroll
    for (int j = ty; j < 32; j += 8)
        Wt[(size_t)(nb + j) * K + kb + tx] = __float2half_rn(t[tx][j]);
}

// ---------------------------------------------------------------------------
// LN1 + shift + window-partition gather -> fp16
// ---------------------------------------------------------------------------
__global__ __launch_bounds__(128)
void ln1_kernel(const float* __restrict__ x, const float* __restrict__ gam,
                const float* __restrict__ bet, __half* __restrict__ out)
{
    int tr = blockIdx.x;
    int bn = tr / NWIN_T;
    int n  = tr - bn * NWIN_T;
    int b  = bn / NWIN;
    int wi = bn - b * NWIN;
    int wy = wi / NWX, wx = wi - wy * NWX;
    int r  = n / WS,   cc = n - r * WS;
    int hs = (wy * WS + r  + SHIFT) % HIMG;
    int ws2= (wx * WS + cc + SHIFT) % WIMG;
    int src = b * LTOK + hs * WIMG + ws2;

    const float* xin = x + (size_t)src * CDIM;
    int tid = threadIdx.x;
    float v0 = xin[tid], v1 = xin[tid + 128], v2 = xin[tid + 256];
    float s  = v0 + v1 + v2;
    float ss = v0*v0 + v1*v1 + v2*v2;
    #pragma unroll
    for (int o = 16; o > 0; o >>= 1) {
        s  += __shfl_down_sync(0xffffffffu, s,  o);
        ss += __shfl_down_sync(0xffffffffu, ss, o);
    }
    __shared__ float red[8];
    __shared__ float mbv[2];
    int w = tid >> 5, l = tid & 31;
    if (l == 0) { red[w] = s; red[4 + w] = ss; }
    __syncthreads();
    if (tid == 0) {
        float S  = red[0] + red[1] + red[2] + red[3];
        float SS = red[4] + red[5] + red[6] + red[7];
        float mean = S * (1.0f / CDIM);
        float var  = SS * (1.0f / CDIM) - mean * mean;
        mbv[0] = mean; mbv[1] = rsqrtf(var + 1e-5f);
    }
    __syncthreads();
    float mean = mbv[0], rstd = mbv[1];
    __half* o = out + (size_t)tr * CDIM;
    o[tid]       = __float2half_rn((v0 - mean) * rstd * gam[tid]       + bet[tid]);
    o[tid + 128] = __float2half_rn((v1 - mean) * rstd * gam[tid + 128] + bet[tid + 128]);
    o[tid + 256] = __float2half_rn((v2 - mean) * rstd * gam[tid + 256] + bet[tid + 256]);
}

// ---------------------------------------------------------------------------
// Fused: window-reverse + roll + residual (y exact fp32), then LN2 -> fp16
// ---------------------------------------------------------------------------
__global__ __launch_bounds__(128)
void mergeln_kernel(const float* __restrict__ x, const float* __restrict__ proj,
                    const float* __restrict__ gam, const float* __restrict__ bet,
                    float* __restrict__ y, __half* __restrict__ out)
{
    int tr = blockIdx.x;
    int b = tr / LTOK, pos = tr - b * LTOK;
    int i = pos / WIMG, j = pos - i * WIMG;
    int ii = (i + HIMG - SHIFT) % HIMG;
    int jj = (j + WIMG - SHIFT) % WIMG;
    int wr = (b * NWIN + (ii / WS) * NWX + (jj / WS)) * NWIN_T + (ii % WS) * WS + (jj % WS);

    const float* xp = x    + (size_t)tr * CDIM;
    const float* pp = proj + (size_t)wr * CDIM;
    int tid = threadIdx.x;
    float v0 = xp[tid]       + pp[tid];
    float v1 = xp[tid + 128] + pp[tid + 128];
    float v2 = xp[tid + 256] + pp[tid + 256];

    float* yp = y + (size_t)tr * CDIM;
    yp[tid] = v0; yp[tid + 128] = v1; yp[tid + 256] = v2;

    float s  = v0 + v1 + v2;
    float ss = v0*v0 + v1*v1 + v2*v2;
    #pragma unroll
    for (int o = 16; o > 0; o >>= 1) {
        s  += __shfl_down_sync(0xffffffffu, s,  o);
        ss += __shfl_down_sync(0xffffffffu, ss, o);
    }
    __shared__ float red[8];
    __shared__ float mbv[2];
    int w = tid >> 5, l = tid & 31;
    if (l == 0) { red[w] = s; red[4 + w] = ss; }
    __syncthreads();
    if (tid == 0) {
        float S  = red[0] + red[1] + red[2] + red[3];
        float SS = red[4] + red[5] + red[6] + red[7];
        float mean = S * (1.0f / CDIM);
        float var  = SS * (1.0f / CDIM) - mean * mean;
        mbv[0] = mean; mbv[1] = rsqrtf(var + 1e-5f);
    }
    __syncthreads();
    float mean = mbv[0], rstd = mbv[1];
    __half* o = out + (size_t)tr * CDIM;
    o[tid]       = __float2half_rn((v0 - mean) * rstd * gam[tid]       + bet[tid]);
    o[tid + 128] = __float2half_rn((v1 - mean) * rstd * gam[tid + 128] + bet[tid + 128]);
    o[tid + 256] = __float2half_rn((v2 - mean) * rstd * gam[tid + 256] + bet[tid + 256]);
}

// ---------------------------------------------------------------------------
// Tensor-core windowed attention: one block (64 thr = 2 warps) per (window, head).
// QK via mma.sync (Q 64x32, K 64x32, 64B rows unswizzled);
// scalar softmax (scale + rpb + mask, fp32);
// PV via mma.sync (P 64x64 fp16 swizzled, Vt 32x64 swizzled).
// Padding rows/cols zero-filled so padded MMA contributions are exactly 0.
// ---------------------------------------------------------------------------
__global__ __launch_bounds__(64)
void attn_kernel(const __half* __restrict__ qkv, const float* __restrict__ mask,
                 const float* __restrict__ rpb, __half* __restrict__ outp)
{
    __shared__ __half Qs[64 * 32];     // 4 KB, 64B rows
    __shared__ __half Ks[64 * 32];     // 4 KB
    __shared__ __half Vt[32 * 64];     // 4 KB, 128B rows, swizzle g^(r&7)
    __shared__ __half Ps[64 * 64];     // 8 KB, 128B rows, swizzle g^(r&7)
    __shared__ float  Sf[64 * 64];     // 16 KB raw scores

    const int bn = blockIdx.x, h = blockIdx.y, tid = threadIdx.x;
    const int lane = tid & 31, warp = tid >> 5;
    const float scale = 0.1767766952966369f;   // 32^-0.5

    // -- zero Q/K/V/P smem (padding correctness)
    {
        uint4 z = make_uint4(0, 0, 0, 0);
        uint4* q4 = (uint4*)Qs;  uint4* k4 = (uint4*)Ks;
        uint4* v4 = (uint4*)Vt;  uint4* p4 = (uint4*)Ps;
        #pragma unroll
        for (int i = 0; i < 4; i++) { q4[tid + 64*i] = z; k4[tid + 64*i] = z; v4[tid + 64*i] = z; }
        #pragma unroll
        for (int i = 0; i < 8; i++) p4[tid + 64*i] = z;
    }
    __syncthreads();

    // -- load Q, K (direct) and V (transposed)
    const size_t basep = (size_t)bn * NWIN_T * (3 * CDIM) + h * HD;
    for (int idx = tid; idx < NWIN_T * 4; idx += 64) {
        int n = idx >> 2, q = (idx & 3) * 8;
        const __half* rowp = qkv + basep + (size_t)n * (3 * CDIM);
        *(uint4*)&Qs[n * 32 + q] = *(const uint4*)(rowp + q);
        *(uint4*)&Ks[n * 32 + q] = *(const uint4*)(rowp + CDIM + q);
    }
    for (int e = tid; e < NWIN_T * 32; e += 64) {
        int tok = e >> 5, ch = e & 31;
        __half v = qkv[basep + (size_t)tok * (3 * CDIM) + 2 * CDIM + ch];
        Vt[ch * 64 + (((tok >> 3) ^ (ch & 7)) << 3) + (tok & 7)] = v;
    }
    __syncthreads();

    const int tsel = lane >> 3, rlo = lane & 7;
    const uint32_t qb = s2u(Qs), kb = s2u(Ks), vb = s2u(Vt), pb = s2u(Ps);

    // -- QK: acc[mt][nt], mt 0-1 (rows warp*32 + mt*16), nt 0-7 (cols nt*8)
    {
        float acc[2][8][4];
        #pragma unroll
        for (int a = 0; a < 2; a++)
            #pragma unroll
            for (int b = 0; b < 8; b++)
                #pragma unroll
                for (int c = 0; c < 4; c++) acc[a][b][c] = 0.0f;

        #pragma unroll
        for (int kst = 0; kst < 2; kst++) {
            uint32_t bfr[8][2];
            #pragma unroll
            for (int p = 0; p < 4; p++) {
                uint32_t row = (uint32_t)(rlo + (tsel >> 1) * 8 + p * 16);
                uint32_t ad  = kb + row * 64 + ((uint32_t)(tsel & 1) + kst * 2u) * 16;
                ldm4(bfr[2*p][0], bfr[2*p][1], bfr[2*p+1][0], bfr[2*p+1][1], ad);
            }
            #pragma unroll
            for (int mt = 0; mt < 2; mt++) {
                uint32_t row = (uint32_t)(warp * 32 + mt * 16 + rlo + (tsel & 1) * 8);
                uint32_t ad  = qb + row * 64 + ((uint32_t)(tsel >> 1) + kst * 2u) * 16;
                uint32_t afr[4];
                ldm4(afr[0], afr[1], afr[2], afr[3], ad);
                #pragma unroll
                for (int nt = 0; nt < 8; nt++)
                    mma_f16(acc[mt][nt], afr, bfr[nt]);
            }
        }
        // store raw scores to Sf (stride 64)
        const int qr = lane >> 2, qc = (lane & 3) * 2;
        #pragma unroll
        for (int mt = 0; mt < 2; mt++) {
            int row = warp * 32 + mt * 16 + qr;
            #pragma unroll
            for (int nt = 0; nt < 8; nt++) {
                int col = nt * 8 + qc;
                *(float2*)&Sf[row * 64 + col]       = make_float2(acc[mt][nt][0], acc[mt][nt][1]);
                *(float2*)&Sf[(row + 8) * 64 + col] = make_float2(acc[mt][nt][2], acc[mt][nt][3]);
            }
        }
    }
    __syncthreads();

    // -- softmax: one thread per query row; writes fp16 probabilities to Ps
    if (tid < NWIN_T) {
        const int n = tid;
        const int r1 = n / WS, c1 = n - r1 * WS;
        const float* mwb = mask + (bn & (NWIN - 1)) * (NWIN_T * NWIN_T) + n * NWIN_T;
        float* srow = Sf + n * 64;

        float mx = -1e30f;
        int r2 = 0, c2 = 0;
        for (int m = 0; m < NWIN_T; m++) {
            int rel = (r1 - r2 + WS - 1) * (2 * WS - 1) + (c1 - c2 + WS - 1);
            float l = srow[m] * scale + rpb[rel * NHEADS + h] + mwb[m];
            srow[m] = l;
            mx = fmaxf(mx, l);
            if (++c2 == WS) { c2 = 0; r2++; }
        }
        float sum = 0.0f;
        for (int m = 0; m < NWIN_T; m++) {
            float e = __expf(srow[m] - mx);
            srow[m] = e; sum += e;
        }
        float inv = 1.0f / sum;
        const uint32_t swn = (uint32_t)n & 7;
        for (int m = 0; m < NWIN_T; m++) {
            uint32_t idx = (uint32_t)n * 64 + ((((uint32_t)m >> 3) ^ swn) << 3) + ((uint32_t)m & 7);
            Ps[idx] = __float2half_rn(srow[m] * inv);
        }
    }
    __syncthreads();

    // -- PV: out[q][ch] = sum_tok P[q][tok] * Vt[ch][tok]; K-dim 64 (4 k-steps)
    {
        float acc[2][4][4];
        #pragma unroll
        for (int a = 0; a < 2; a++)
            #pragma unroll
            for (int b = 0; b < 4; b++)
                #pragma unroll
                for (int c = 0; c < 4; c++) acc[a][b][c] = 0.0f;

        #pragma unroll
        for (int kst = 0; kst < 4; kst++) {
            uint32_t bfr[4][2];
            #pragma unroll
            for (int p = 0; p < 2; p++) {
                uint32_t row = (uint32_t)(rlo + (tsel >> 1) * 8 + p * 16);
                uint32_t ad  = vb + row * 128 +
                               ((((uint32_t)(tsel & 1) + kst * 2u) ^ (uint32_t)rlo) << 4);
                ldm4(bfr[2*p][0], bfr[2*p][1], bfr[2*p+1][0], bfr[2*p+1][1], ad);
            }
            #pragma unroll
            for (int mt = 0; mt < 2; mt++) {
                uint32_t row = (uint32_t)(warp * 32 + mt * 16 + rlo + (tsel & 1) * 8);
                uint32_t ad  = pb + row * 128 +
                               ((((uint32_t)(tsel >> 1) + kst * 2u) ^ (uint32_t)rlo) << 4);
                uint32_t afr[4];
                ldm4(afr[0], afr[1], afr[2], afr[3], ad);
                #pragma unroll
                for (int nt = 0; nt < 4; nt++)
                    mma_f16(acc[mt][nt], afr, bfr[nt]);
            }
        }
        // epilogue: rows < 49 only
        const int qr = lane >> 2, qc = (lane & 3) * 2;
        #pragma unroll
        for (int mt = 0; mt < 2; mt++) {
            int row = warp * 32 + mt * 16 + qr;
            #pragma unroll
            for (int nt = 0; nt < 4; nt++) {
                int col = nt * 8 + qc;
                if (row < NWIN_T)
                    *(__half2*)(outp + (size_t)(bn * NWIN_T + row) * CDIM + h * HD + col)
                        = __floats2half2_rn(acc[mt][nt][0], acc[mt][nt][1]);
                if (row + 8 < NWIN_T)
                    *(__half2*)(outp + (size_t)(bn * NWIN_T + row + 8) * CDIM + h * HD + col)
                        = __floats2half2_rn(acc[mt][nt][2], acc[mt][nt][3]);
            }
        }
    }
}

// ---------------------------------------------------------------------------
// Launch
// ---------------------------------------------------------------------------
extern "C" void kernel_launch(void* const* d_in, const int* in_sizes, int n_in,
                              void* d_out, int out_size)
{
    const float* x        = (const float*)d_in[0];
    const float* attnmask = (const float*)d_in[1];
    const float* norm1_g  = (const float*)d_in[2];
    const float* norm1_b  = (const float*)d_in[3];
    const float* qkv_w    = (const float*)d_in[4];
    const float* qkv_b    = (const float*)d_in[5];
    const float* rpb      = (const float*)d_in[6];
    const float* proj_w   = (const float*)d_in[7];
    const float* proj_b   = (const float*)d_in[8];
    const float* norm2_g  = (const float*)d_in[9];
    const float* norm2_b  = (const float*)d_in[10];
    const float* fc1_w    = (const float*)d_in[11];
    const float* fc1_b    = (const float*)d_in[12];
    const float* fc2_w    = (const float*)d_in[13];
    const float* fc2_b    = (const float*)d_in[14];
    (void)in_sizes; (void)n_in; (void)out_size;

    float *projb, *y;
    __half *qkvbuf, *win, *att, *h2, *mlp, *wq, *wp, *w1, *w2;
    cudaGetSymbolAddress((void**)&qkvbuf, g_qkv);
    cudaGetSymbolAddress((void**)&projb,  g_proj);
    cudaGetSymbolAddress((void**)&y,      g_y);
    cudaGetSymbolAddress((void**)&win,    g_win);
    cudaGetSymbolAddress((void**)&att,    g_att);
    cudaGetSymbolAddress((void**)&h2,     g_h2);
    cudaGetSymbolAddress((void**)&mlp,    g_mlp);
    cudaGetSymbolAddress((void**)&wq,     g_wq);
    cudaGetSymbolAddress((void**)&wp,     g_wp);
    cudaGetSymbolAddress((void**)&w1,     g_w1);
    cudaGetSymbolAddress((void**)&w2,     g_w2);

    cudaFuncSetAttribute(mma_gemm<0>, cudaFuncAttributeMaxDynamicSharedMemorySize, GEMM_SMEM);
    cudaFuncSetAttribute(mma_gemm<1>, cudaFuncAttributeMaxDynamicSharedMemorySize, GEMM_SMEM);
    cudaFuncSetAttribute(mma_gemm<2>, cudaFuncAttributeMaxDynamicSharedMemorySize, GEMM_SMEM);
    cudaFuncSetAttribute(mma_gemm<3>, cudaFuncAttributeMaxDynamicSharedMemorySize, GEMM_SMEM);

    // 0. weight transpose + fp16 round
    wtrans_kernel<<<dim3(3*CDIM/32, CDIM/32), 256>>>(qkv_w,  wq, CDIM, 3*CDIM);
    wtrans_kernel<<<dim3(CDIM/32,   CDIM/32), 256>>>(proj_w, wp, CDIM, CDIM);
    wtrans_kernel<<<dim3(HID/32,    CDIM/32), 256>>>(fc1_w,  w1, CDIM, HID);
    wtrans_kernel<<<dim3(CDIM/32,   HID/32),  256>>>(fc2_w,  w2, HID,  CDIM);

    // 1. LN1 + shift + window partition (fp16)
    ln1_kernel<<<MTOK, 128>>>(x, norm1_g, norm1_b, win);

    // 2. QKV GEMM -> fp16
    mma_gemm<3><<<dim3(9, MTOK/128), 256, GEMM_SMEM>>>(
        win, wq, qkv_b, nullptr, nullptr, qkvbuf, 3*CDIM, CDIM);

    // 3. Tensor-core windowed attention
    attn_kernel<<<dim3(BN, NHEADS), 64>>>(qkvbuf, attnmask, rpb, att);

    // 4. proj GEMM -> fp32
    mma_gemm<0><<<dim3(3, MTOK/128), 256, GEMM_SMEM>>>(
        att, wp, proj_b, nullptr, projb, nullptr, CDIM, CDIM);

    // 5+6. reverse + roll + residual + LN2 (fused)
    mergeln_kernel<<<MTOK, 128>>>(x, projb, norm2_g, norm2_b, y, h2);

    // 7. fc1 + GELU (fp16 out)
    mma_gemm<1><<<dim3(12, MTOK/128), 256, GEMM_SMEM>>>(
        h2, w1, fc1_b, nullptr, nullptr, mlp, HID, CDIM);

    // 8. fc2 + residual -> d_out
    mma_gemm<2><<<dim3(3, MTOK/128), 256, GEMM_SMEM>>>(
        mlp, w2, fc2_b, y, (float*)d_out, nullptr, CDIM, HID);
}